// round 4
// baseline (speedup 1.0000x reference)
#include <cuda_runtime.h>
#include <cuda_bf16.h>
#include <cstdint>

static constexpr int BDIM = 4096;
static constexpr int IDIM = 1024;
static constexpr int HDIM = 2048;
static constexpr int NSTEPS = 10;
static constexpr float DT = 0.1f;

static constexpr int BM = 128, BN = 128, BK = 32;
static constexpr int STAGES = 4;
static constexpr int NT = 256;
// stage layout: [A_hi 8K | A_lo 8K | B_hi 8K | B_lo 8K] = 32 KB
static constexpr int PLANE_BYTES = BM * BK * 2;           // 8 KB
static constexpr int STAGE_BYTES = 4 * PLANE_BYTES;       // 32 KB
static constexpr int OFF_COLV = STAGES * STAGE_BYTES;     // 128 KB
static constexpr int SMEM_TOTAL = OFF_COLV + BN * 4 + 16;

__device__ float g_ihb  [BDIM * HDIM];
__device__ float g_hfull[BDIM * HDIM];
__device__ __nv_bfloat16 g_hhiA[BDIM * HDIM];
__device__ __nv_bfloat16 g_hloA[BDIM * HDIM];
__device__ __nv_bfloat16 g_hhiB[BDIM * HDIM];
__device__ __nv_bfloat16 g_hloB[BDIM * HDIM];
__device__ __nv_bfloat16 g_xhi [BDIM * IDIM];
__device__ __nv_bfloat16 g_xlo [BDIM * IDIM];
__device__ __nv_bfloat16 g_wihhi[HDIM * IDIM];
__device__ __nv_bfloat16 g_wihlo[HDIM * IDIM];
__device__ __nv_bfloat16 g_whhhi[HDIM * HDIM];
__device__ __nv_bfloat16 g_whhlo[HDIM * HDIM];

__device__ __forceinline__ uint32_t smem_u32(const void* p) {
    uint32_t a;
    asm("{ .reg .u64 t; cvta.to.shared.u64 t, %1; cvt.u32.u64 %0, t; }" : "=r"(a) : "l"(p));
    return a;
}
__device__ __forceinline__ void cp16(uint32_t dst, const void* src) {
    asm volatile("cp.async.cg.shared.global [%0], [%1], 16;" :: "r"(dst), "l"(src) : "memory");
}
__device__ __forceinline__ void cp_commit() { asm volatile("cp.async.commit_group;" ::: "memory"); }
template <int N> __device__ __forceinline__ void cp_wait() {
    asm volatile("cp.async.wait_group %0;" :: "n"(N) : "memory");
}
__device__ __forceinline__ float tanh_acc(float x) {
    float ax = fabsf(x);
    float e = __expf(-2.0f * ax);
    float t = (1.0f - e) / (1.0f + e);
    return copysignf(t, x);
}
__device__ __forceinline__ void mma_bf16(float* c, const uint32_t* a, const uint32_t* b) {
    asm volatile(
        "mma.sync.aligned.m16n8k16.row.col.f32.bf16.bf16.f32 "
        "{%0,%1,%2,%3},{%4,%5,%6,%7},{%8,%9},{%0,%1,%2,%3};"
        : "+f"(c[0]), "+f"(c[1]), "+f"(c[2]), "+f"(c[3])
        : "r"(a[0]), "r"(a[1]), "r"(a[2]), "r"(a[3]), "r"(b[0]), "r"(b[1]));
}

// fp32 -> (hi, lo) bf16 planes; exact-ish split: hi = rn(x), lo = rn(x - hi)
__global__ void split_kernel(const float* __restrict__ in,
                             __nv_bfloat16* __restrict__ hi,
                             __nv_bfloat16* __restrict__ lo, int n4) {
    int i = blockIdx.x * blockDim.x + threadIdx.x;
    int s = gridDim.x * blockDim.x;
    for (; i < n4; i += s) {
        float4 v = reinterpret_cast<const float4*>(in)[i];
        __nv_bfloat162 h01, h23, l01, l23;
        h01.x = __float2bfloat16(v.x); l01.x = __float2bfloat16(v.x - __bfloat162float(h01.x));
        h01.y = __float2bfloat16(v.y); l01.y = __float2bfloat16(v.y - __bfloat162float(h01.y));
        h23.x = __float2bfloat16(v.z); l23.x = __float2bfloat16(v.z - __bfloat162float(h23.x));
        h23.y = __float2bfloat16(v.w); l23.y = __float2bfloat16(v.w - __bfloat162float(h23.y));
        reinterpret_cast<__nv_bfloat162*>(hi)[i * 2]     = h01;
        reinterpret_cast<__nv_bfloat162*>(hi)[i * 2 + 1] = h23;
        reinterpret_cast<__nv_bfloat162*>(lo)[i * 2]     = l01;
        reinterpret_cast<__nv_bfloat162*>(lo)[i * 2 + 1] = l23;
    }
}
__global__ void prep_h_kernel(const float* __restrict__ h0, float* __restrict__ hf,
                              __nv_bfloat16* __restrict__ hi,
                              __nv_bfloat16* __restrict__ lo, int n4) {
    int i = blockIdx.x * blockDim.x + threadIdx.x;
    int s = gridDim.x * blockDim.x;
    for (; i < n4; i += s) {
        float4 v = reinterpret_cast<const float4*>(h0)[i];
        reinterpret_cast<float4*>(hf)[i] = v;
        __nv_bfloat162 h01, h23, l01, l23;
        h01.x = __float2bfloat16(v.x); l01.x = __float2bfloat16(v.x - __bfloat162float(h01.x));
        h01.y = __float2bfloat16(v.y); l01.y = __float2bfloat16(v.y - __bfloat162float(h01.y));
        h23.x = __float2bfloat16(v.z); l23.x = __float2bfloat16(v.z - __bfloat162float(h23.x));
        h23.y = __float2bfloat16(v.w); l23.y = __float2bfloat16(v.w - __bfloat162float(h23.y));
        reinterpret_cast<__nv_bfloat162*>(hi)[i * 2]     = h01;
        reinterpret_cast<__nv_bfloat162*>(hi)[i * 2 + 1] = h23;
        reinterpret_cast<__nv_bfloat162*>(lo)[i * 2]     = l01;
        reinterpret_cast<__nv_bfloat162*>(lo)[i * 2 + 1] = l23;
    }
}

// D[m][n] = sum_k A[m][k]*W[n][k], A = Ahi+Alo, W = Whi+Wlo (bf16x3: hh + hl + lh)
// STEP=false: out_full = D + b_ih[n] + b_hh[n]
// STEP=true : pre = D + ihb; hn = dec*hfull + (1-dec)*tanh(pre)
//             out_full = hn; out_hi/out_lo = bf16 split of hn
template <bool STEP>
__global__ __launch_bounds__(NT, 1)
void gemm_kernel(const __nv_bfloat16* __restrict__ Ahi, const __nv_bfloat16* __restrict__ Alo,
                 const __nv_bfloat16* __restrict__ Whi, const __nv_bfloat16* __restrict__ Wlo,
                 int K,
                 const float* __restrict__ aux0,   // STEP: ihb      | !STEP: b_ih
                 const float* __restrict__ aux1,   // STEP: hfull_in | !STEP: b_hh
                 const float* __restrict__ tau,
                 float* __restrict__ out_full,
                 __nv_bfloat16* __restrict__ out_hi, __nv_bfloat16* __restrict__ out_lo,
                 int ldo) {
    extern __shared__ char sm[];
    float* colv = (float*)(sm + OFF_COLV);
    const uint32_t sb = smem_u32(sm);
    const int tid = threadIdx.x;
    const int lane = tid & 31;
    const int wid = tid >> 5;
    const int wm = wid >> 2;
    const int wn = wid & 3;
    const int g = lane >> 2;
    const int tig = lane & 3;
    const int n0 = blockIdx.x * BN;
    const int m0 = blockIdx.y * BM;

    for (int j = tid; j < BN; j += NT)
        colv[j] = STEP ? __expf(-DT / tau[n0 + j]) : (aux0[n0 + j] + aux1[n0 + j]);

    // staging: idx = tid + t*NT over [0,1024): plane p=idx>>9, row r, 16B-quad j
    const char* asrc[4]; const char* bsrc[4];
    uint32_t adst[4], bdst[4];
    #pragma unroll
    for (int t = 0; t < 4; t++) {
        int idx = tid + t * NT;
        int p = idx >> 9, rem = idx & 511, r = rem >> 2, j = rem & 3;
        uint32_t sw = (uint32_t)(r * 64 + ((j ^ ((r >> 1) & 3)) << 4));
        adst[t] = p * PLANE_BYTES + sw;
        bdst[t] = 2 * PLANE_BYTES + p * PLANE_BYTES + sw;
        asrc[t] = (const char*)(p ? Alo : Ahi) + ((size_t)(m0 + r) * K + j * 8) * 2;
        bsrc[t] = (const char*)(p ? Wlo : Whi) + ((size_t)(n0 + r) * K + j * 8) * 2;
    }

    const int NK = K / BK;
    auto stage = [&](int i) {
        const uint32_t base = sb + (i % STAGES) * STAGE_BYTES;
        const int koff = i * BK * 2;
        #pragma unroll
        for (int t = 0; t < 4; t++) {
            cp16(base + adst[t], asrc[t] + koff);
            cp16(base + bdst[t], bsrc[t] + koff);
        }
    };

    float acc[4][4][4];
    #pragma unroll
    for (int mt = 0; mt < 4; mt++)
        #pragma unroll
        for (int nt = 0; nt < 4; nt++)
            #pragma unroll
            for (int q = 0; q < 4; q++) acc[mt][nt][q] = 0.0f;

    #pragma unroll
    for (int i = 0; i < STAGES - 1; i++)
        if (i < NK) { stage(i); cp_commit(); }

    for (int i = 0; i < NK; i++) {
        const int rem = NK - 1 - i;
        if      (rem >= STAGES - 1) cp_wait<STAGES - 2>();
        else if (rem == 2)          cp_wait<2>();
        else if (rem == 1)          cp_wait<1>();
        else                        cp_wait<0>();
        __syncthreads();
        if (i + STAGES - 1 < NK) { stage(i + STAGES - 1); cp_commit(); }

        const char* stg = sm + (i % STAGES) * STAGE_BYTES;
        #pragma unroll
        for (int ks = 0; ks < 2; ks++) {
            uint32_t ah[4][4], al[4][4], bh[4][2], bl[4][2];
            const int w0 = ks * 8 + tig;
            const int w2 = w0 + 4;
            #pragma unroll
            for (int mt = 0; mt < 4; mt++) {
                const int r0 = wm * 64 + mt * 16 + g;
                const int r1 = r0 + 8;
                const int q0 = (r0 >> 1) & 3, q1 = (r1 >> 1) & 3;
                const uint32_t a00 = r0 * 64 + ((w0 ^ (q0 << 2)) << 2);
                const uint32_t a10 = r1 * 64 + ((w0 ^ (q1 << 2)) << 2);
                const uint32_t a02 = r0 * 64 + ((w2 ^ (q0 << 2)) << 2);
                const uint32_t a12 = r1 * 64 + ((w2 ^ (q1 << 2)) << 2);
                ah[mt][0] = *(const uint32_t*)(stg + a00);
                ah[mt][1] = *(const uint32_t*)(stg + a10);
                ah[mt][2] = *(const uint32_t*)(stg + a02);
                ah[mt][3] = *(const uint32_t*)(stg + a12);
                al[mt][0] = *(const uint32_t*)(stg + PLANE_BYTES + a00);
                al[mt][1] = *(const uint32_t*)(stg + PLANE_BYTES + a10);
                al[mt][2] = *(const uint32_t*)(stg + PLANE_BYTES + a02);
                al[mt][3] = *(const uint32_t*)(stg + PLANE_BYTES + a12);
            }
            #pragma unroll
            for (int nt = 0; nt < 4; nt++) {
                const int rn = wn * 32 + nt * 8 + g;
                const int qn = (rn >> 1) & 3;
                const uint32_t b0 = rn * 64 + ((w0 ^ (qn << 2)) << 2);
                const uint32_t b1 = rn * 64 + ((w2 ^ (qn << 2)) << 2);
                bh[nt][0] = *(const uint32_t*)(stg + 2 * PLANE_BYTES + b0);
                bh[nt][1] = *(const uint32_t*)(stg + 2 * PLANE_BYTES + b1);
                bl[nt][0] = *(const uint32_t*)(stg + 3 * PLANE_BYTES + b0);
                bl[nt][1] = *(const uint32_t*)(stg + 3 * PLANE_BYTES + b1);
            }
            #pragma unroll
            for (int mt = 0; mt < 4; mt++)
                #pragma unroll
                for (int nt = 0; nt < 4; nt++) {
                    mma_bf16(acc[mt][nt], ah[mt], bh[nt]);
                    mma_bf16(acc[mt][nt], ah[mt], bl[nt]);
                    mma_bf16(acc[mt][nt], al[mt], bh[nt]);
                }
        }
        __syncthreads();
    }

    #pragma unroll
    for (int mt = 0; mt < 4; mt++) {
        #pragma unroll
        for (int h = 0; h < 2; h++) {
            const int row = m0 + wm * 64 + mt * 16 + g + h * 8;
            const size_t base = (size_t)row * ldo;
            #pragma unroll
            for (int nt = 0; nt < 4; nt++) {
                const int col = n0 + wn * 32 + nt * 8 + tig * 2;
                const float d0 = acc[mt][nt][h * 2 + 0];
                const float d1 = acc[mt][nt][h * 2 + 1];
                if (STEP) {
                    float2 ib = *reinterpret_cast<const float2*>(aux0 + base + col);
                    float2 hf = *reinterpret_cast<const float2*>(aux1 + base + col);
                    const float dc0 = colv[col - n0];
                    const float dc1 = colv[col - n0 + 1];
                    const float hn0 = dc0 * hf.x + (1.0f - dc0) * tanh_acc(d0 + ib.x);
                    const float hn1 = dc1 * hf.y + (1.0f - dc1) * tanh_acc(d1 + ib.y);
                    *reinterpret_cast<float2*>(out_full + base + col) = make_float2(hn0, hn1);
                    __nv_bfloat162 hp, lp;
                    hp.x = __float2bfloat16(hn0);
                    hp.y = __float2bfloat16(hn1);
                    lp.x = __float2bfloat16(hn0 - __bfloat162float(hp.x));
                    lp.y = __float2bfloat16(hn1 - __bfloat162float(hp.y));
                    *reinterpret_cast<__nv_bfloat162*>(out_hi + base + col) = hp;
                    *reinterpret_cast<__nv_bfloat162*>(out_lo + base + col) = lp;
                } else {
                    float2 o = make_float2(d0 + colv[col - n0], d1 + colv[col - n0 + 1]);
                    *reinterpret_cast<float2*>(out_full + base + col) = o;
                }
            }
        }
    }
}

extern "C" void kernel_launch(void* const* d_in, const int* in_sizes, int n_in,
                              void* d_out, int out_size) {
    (void)in_sizes; (void)n_in; (void)out_size;
    const float* x   = (const float*)d_in[0];
    const float* h0  = (const float*)d_in[1];
    const float* Wih = (const float*)d_in[2];
    const float* bih = (const float*)d_in[3];
    const float* Whh = (const float*)d_in[4];
    const float* bhh = (const float*)d_in[5];
    const float* tau = (const float*)d_in[6];
    float* out = (float*)d_out;

    float *p_ihb, *p_hfull;
    __nv_bfloat16 *p_hhiA, *p_hloA, *p_hhiB, *p_hloB;
    __nv_bfloat16 *p_xhi, *p_xlo, *p_wihhi, *p_wihlo, *p_whhhi, *p_whhlo;
    cudaGetSymbolAddress((void**)&p_ihb, g_ihb);
    cudaGetSymbolAddress((void**)&p_hfull, g_hfull);
    cudaGetSymbolAddress((void**)&p_hhiA, g_hhiA);
    cudaGetSymbolAddress((void**)&p_hloA, g_hloA);
    cudaGetSymbolAddress((void**)&p_hhiB, g_hhiB);
    cudaGetSymbolAddress((void**)&p_hloB, g_hloB);
    cudaGetSymbolAddress((void**)&p_xhi, g_xhi);
    cudaGetSymbolAddress((void**)&p_xlo, g_xlo);
    cudaGetSymbolAddress((void**)&p_wihhi, g_wihhi);
    cudaGetSymbolAddress((void**)&p_wihlo, g_wihlo);
    cudaGetSymbolAddress((void**)&p_whhhi, g_whhhi);
    cudaGetSymbolAddress((void**)&p_whhlo, g_whhlo);

    cudaFuncSetAttribute(gemm_kernel<false>, cudaFuncAttributeMaxDynamicSharedMemorySize, SMEM_TOTAL);
    cudaFuncSetAttribute(gemm_kernel<true>,  cudaFuncAttributeMaxDynamicSharedMemorySize, SMEM_TOTAL);

    split_kernel<<<512, 256>>>(x,   p_xhi,   p_xlo,   BDIM * IDIM / 4);
    split_kernel<<<512, 256>>>(Wih, p_wihhi, p_wihlo, HDIM * IDIM / 4);
    split_kernel<<<512, 256>>>(Whh, p_whhhi, p_whhlo, HDIM * HDIM / 4);
    prep_h_kernel<<<512, 256>>>(h0, p_hfull, p_hhiA, p_hloA, BDIM * HDIM / 4);

    dim3 grid(HDIM / BN, BDIM / BM);
    // ih = x @ Wih^T + b_ih + b_hh (both biases folded into the drive)
    gemm_kernel<false><<<grid, NT, SMEM_TOTAL>>>(p_xhi, p_xlo, p_wihhi, p_wihlo, IDIM,
                                                 bih, bhh, nullptr,
                                                 p_ihb, nullptr, nullptr, HDIM);
    __nv_bfloat16 *hi_in = p_hhiA, *lo_in = p_hloA;
    __nv_bfloat16 *hi_out = p_hhiB, *lo_out = p_hloB;
    for (int s = 0; s < NSTEPS; s++) {
        float* full_dst = (s == NSTEPS - 1) ? out : p_hfull;
        gemm_kernel<true><<<grid, NT, SMEM_TOTAL>>>(hi_in, lo_in, p_whhhi, p_whhlo, HDIM,
                                                    p_ihb, p_hfull, tau,
                                                    full_dst, hi_out, lo_out, HDIM);
        __nv_bfloat16* t;
        t = hi_in; hi_in = hi_out; hi_out = t;
        t = lo_in; lo_in = lo_out; lo_out = t;
    }
}

// round 5
// speedup vs baseline: 1.3297x; 1.3297x over previous
#include <cuda_runtime.h>
#include <cuda_bf16.h>
#include <cstdint>

static constexpr int BDIM = 4096;
static constexpr int IDIM = 1024;
static constexpr int HDIM = 2048;
static constexpr int NSTEPS = 10;
static constexpr float DT = 0.1f;

static constexpr int BM = 128, BN = 64, BK = 32;
static constexpr int STAGES = 4;
static constexpr int NT = 256;
// stage: [A_hi 8K | A_lo 8K | B_hi 4K | B_lo 4K] = 24 KB
static constexpr int A_PLANE = BM * BK * 2;            // 8 KB
static constexpr int B_PLANE = BN * BK * 2;            // 4 KB
static constexpr int STAGE_BYTES = 2 * A_PLANE + 2 * B_PLANE;   // 24 KB
static constexpr int OFF_BPL = 2 * A_PLANE;            // 16 KB into stage
static constexpr int OFF_COLV = STAGES * STAGE_BYTES;  // 96 KB
static constexpr int SMEM_TOTAL = OFF_COLV + BN * 4 + 16;

__device__ float g_ihb  [BDIM * HDIM];
__device__ float g_hfull[BDIM * HDIM];
__device__ __nv_bfloat16 g_hhiA[BDIM * HDIM];
__device__ __nv_bfloat16 g_hloA[BDIM * HDIM];
__device__ __nv_bfloat16 g_hhiB[BDIM * HDIM];
__device__ __nv_bfloat16 g_hloB[BDIM * HDIM];
__device__ __nv_bfloat16 g_xhi [BDIM * IDIM];
__device__ __nv_bfloat16 g_xlo [BDIM * IDIM];
__device__ __nv_bfloat16 g_wihhi[HDIM * IDIM];
__device__ __nv_bfloat16 g_wihlo[HDIM * IDIM];
__device__ __nv_bfloat16 g_whhhi[HDIM * HDIM];
__device__ __nv_bfloat16 g_whhlo[HDIM * HDIM];

__device__ __forceinline__ uint32_t smem_u32(const void* p) {
    uint32_t a;
    asm("{ .reg .u64 t; cvta.to.shared.u64 t, %1; cvt.u32.u64 %0, t; }" : "=r"(a) : "l"(p));
    return a;
}
__device__ __forceinline__ void cp16(uint32_t dst, const void* src) {
    asm volatile("cp.async.cg.shared.global [%0], [%1], 16;" :: "r"(dst), "l"(src) : "memory");
}
__device__ __forceinline__ void cp_commit() { asm volatile("cp.async.commit_group;" ::: "memory"); }
template <int N> __device__ __forceinline__ void cp_wait() {
    asm volatile("cp.async.wait_group %0;" :: "n"(N) : "memory");
}
__device__ __forceinline__ float tanh_acc(float x) {
    float ax = fabsf(x);
    float e = __expf(-2.0f * ax);
    float t = (1.0f - e) / (1.0f + e);
    return copysignf(t, x);
}
__device__ __forceinline__ void mma_bf16(float* c, const uint32_t* a, const uint32_t* b) {
    asm volatile(
        "mma.sync.aligned.m16n8k16.row.col.f32.bf16.bf16.f32 "
        "{%0,%1,%2,%3},{%4,%5,%6,%7},{%8,%9},{%0,%1,%2,%3};"
        : "+f"(c[0]), "+f"(c[1]), "+f"(c[2]), "+f"(c[3])
        : "r"(a[0]), "r"(a[1]), "r"(a[2]), "r"(a[3]), "r"(b[0]), "r"(b[1]));
}
__device__ __forceinline__ void ldsm4(uint32_t* r, uint32_t addr) {
    asm volatile("ldmatrix.sync.aligned.m8n8.x4.shared.b16 {%0,%1,%2,%3}, [%4];"
                 : "=r"(r[0]), "=r"(r[1]), "=r"(r[2]), "=r"(r[3]) : "r"(addr));
}
__device__ __forceinline__ void split1(float v, __nv_bfloat16& h, __nv_bfloat16& l) {
    h = __float2bfloat16(v);
    l = __float2bfloat16(v - __bfloat162float(h));
}

// One prep kernel: split x / Wih / Whh, copy+split h0.
__global__ void prep_all_kernel(const float* __restrict__ x,
                                const float* __restrict__ Wih,
                                const float* __restrict__ Whh,
                                const float* __restrict__ h0,
                                __nv_bfloat16* __restrict__ xhi, __nv_bfloat16* __restrict__ xlo,
                                __nv_bfloat16* __restrict__ wihhi, __nv_bfloat16* __restrict__ wihlo,
                                __nv_bfloat16* __restrict__ whhhi, __nv_bfloat16* __restrict__ whhlo,
                                float* __restrict__ hfull,
                                __nv_bfloat16* __restrict__ hhi, __nv_bfloat16* __restrict__ hlo) {
    const int stride = gridDim.x * blockDim.x;
    const int t0 = blockIdx.x * blockDim.x + threadIdx.x;
    auto split4 = [](float4 v, __nv_bfloat16* hi, __nv_bfloat16* lo, int i) {
        __nv_bfloat162 h01, h23, l01, l23;
        split1(v.x, h01.x, l01.x); split1(v.y, h01.y, l01.y);
        split1(v.z, h23.x, l23.x); split1(v.w, h23.y, l23.y);
        reinterpret_cast<__nv_bfloat162*>(hi)[i * 2]     = h01;
        reinterpret_cast<__nv_bfloat162*>(hi)[i * 2 + 1] = h23;
        reinterpret_cast<__nv_bfloat162*>(lo)[i * 2]     = l01;
        reinterpret_cast<__nv_bfloat162*>(lo)[i * 2 + 1] = l23;
    };
    for (int i = t0; i < BDIM * IDIM / 4; i += stride)
        split4(reinterpret_cast<const float4*>(x)[i], xhi, xlo, i);
    for (int i = t0; i < HDIM * IDIM / 4; i += stride)
        split4(reinterpret_cast<const float4*>(Wih)[i], wihhi, wihlo, i);
    for (int i = t0; i < HDIM * HDIM / 4; i += stride)
        split4(reinterpret_cast<const float4*>(Whh)[i], whhhi, whhlo, i);
    for (int i = t0; i < BDIM * HDIM / 4; i += stride) {
        float4 v = reinterpret_cast<const float4*>(h0)[i];
        reinterpret_cast<float4*>(hfull)[i] = v;
        split4(v, hhi, hlo, i);
    }
}

// D[m][n] = sum_k A[m][k]*W[n][k]; bf16x3 (hh + hl + lh), fp32 acc.
template <bool STEP>
__global__ __launch_bounds__(NT, 2)
void gemm_kernel(const __nv_bfloat16* __restrict__ Ahi, const __nv_bfloat16* __restrict__ Alo,
                 const __nv_bfloat16* __restrict__ Whi, const __nv_bfloat16* __restrict__ Wlo,
                 int K,
                 const float* __restrict__ aux0,   // STEP: ihb      | !STEP: b_ih
                 const float* __restrict__ aux1,   // STEP: hfull_in | !STEP: b_hh
                 const float* __restrict__ tau,
                 float* __restrict__ out_full,
                 __nv_bfloat16* __restrict__ out_hi, __nv_bfloat16* __restrict__ out_lo,
                 int ldo) {
    extern __shared__ char sm[];
    float* colv = (float*)(sm + OFF_COLV);
    const uint32_t sb = smem_u32(sm);
    const int tid = threadIdx.x;
    const int lane = tid & 31;
    const int wid = tid >> 5;
    const int wm = wid >> 2;      // 0..1
    const int wn = wid & 3;       // 0..3
    const int g = lane >> 2;
    const int tig = lane & 3;
    const int n0 = blockIdx.x * BN;
    const int m0 = blockIdx.y * BM;

    for (int j = tid; j < BN; j += NT)
        colv[j] = STEP ? __expf(-DT / tau[n0 + j]) : (aux0[n0 + j] + aux1[n0 + j]);

    // ldmatrix lane geometry: tile = lane>>3 → (rowhalf = bit0, khalf = bit1)
    const int lrow = ((lane >> 3) & 1) * 8 + (lane & 7);   // row within 16-row frag
    const int lkh  = (lane >> 4);                          // k-half (0/1)

    // staging: 1536 16B-chunks/stage (A:1024, B:512), 6 per thread
    const char* gsrc[6];
    uint32_t sdst[6];
    #pragma unroll
    for (int t = 0; t < 6; t++) {
        int idx = tid + t * NT;
        if (idx < 1024) {
            int p = idx >> 9, rem = idx & 511, r = rem >> 2, j = rem & 3;
            sdst[t] = p * A_PLANE + (uint32_t)(r * 64 + ((j ^ ((r >> 1) & 3)) << 4));
            gsrc[t] = (const char*)(p ? Alo : Ahi) + ((size_t)(m0 + r) * K + j * 8) * 2;
        } else {
            int q = idx - 1024;
            int p = q >> 8, rem = q & 255, r = rem >> 2, j = rem & 3;
            sdst[t] = OFF_BPL + p * B_PLANE + (uint32_t)(r * 64 + ((j ^ ((r >> 1) & 3)) << 4));
            gsrc[t] = (const char*)(p ? Wlo : Whi) + ((size_t)(n0 + r) * K + j * 8) * 2;
        }
    }

    const int NK = K / BK;
    auto stage = [&](int i) {
        const uint32_t base = sb + (i % STAGES) * STAGE_BYTES;
        const int koff = i * BK * 2;
        #pragma unroll
        for (int t = 0; t < 6; t++) cp16(base + sdst[t], gsrc[t] + koff);
    };

    float acc[4][2][4];
    #pragma unroll
    for (int mt = 0; mt < 4; mt++)
        #pragma unroll
        for (int nt = 0; nt < 2; nt++)
            #pragma unroll
            for (int q = 0; q < 4; q++) acc[mt][nt][q] = 0.0f;

    // precompute per-lane swizzled LDSM offsets (within a stage buffer)
    // A: frag (mt, pl, ks): row = wm*64 + mt*16 + lrow
    uint32_t aoff[4][2];   // [mt][ks] ; plane adds A_PLANE
    #pragma unroll
    for (int mt = 0; mt < 4; mt++) {
        const int r = wm * 64 + mt * 16 + lrow;
        const int q = (r >> 1) & 3;
        #pragma unroll
        for (int ks = 0; ks < 2; ks++) {
            const int j = ks * 2 + lkh;
            aoff[mt][ks] = (uint32_t)(r * 64 + ((j ^ q) << 4));
        }
    }
    uint32_t boff[2];      // [ks] ; covers both nt via x4
    {
        const int r = wn * 16 + lrow;
        const int q = (r >> 1) & 3;
        #pragma unroll
        for (int ks = 0; ks < 2; ks++) {
            const int j = ks * 2 + lkh;
            boff[ks] = OFF_BPL + (uint32_t)(r * 64 + ((j ^ q) << 4));
        }
    }

    #pragma unroll
    for (int i = 0; i < STAGES - 1; i++)
        if (i < NK) { stage(i); cp_commit(); }

    for (int i = 0; i < NK; i++) {
        const int rem = NK - 1 - i;
        if      (rem >= 2) cp_wait<2>();
        else if (rem == 1) cp_wait<1>();
        else               cp_wait<0>();
        __syncthreads();
        if (i + STAGES - 1 < NK) { stage(i + STAGES - 1); cp_commit(); }

        const uint32_t stg = sb + (i % STAGES) * STAGE_BYTES;
        #pragma unroll
        for (int ks = 0; ks < 2; ks++) {
            uint32_t ah[4][4], al[4][4], bhx[4], blx[4];
            #pragma unroll
            for (int mt = 0; mt < 4; mt++) {
                ldsm4(ah[mt], stg + aoff[mt][ks]);
                ldsm4(al[mt], stg + A_PLANE + aoff[mt][ks]);
            }
            ldsm4(bhx, stg + boff[ks]);
            ldsm4(blx, stg + B_PLANE + boff[ks]);
            // b-frag for nt: {reg[nt], reg[2+nt]}
            uint32_t bh0[2] = { bhx[0], bhx[2] }, bh1[2] = { bhx[1], bhx[3] };
            uint32_t bl0[2] = { blx[0], blx[2] }, bl1[2] = { blx[1], blx[3] };
            #pragma unroll
            for (int mt = 0; mt < 4; mt++) {
                mma_bf16(acc[mt][0], ah[mt], bh0);
                mma_bf16(acc[mt][0], ah[mt], bl0);
                mma_bf16(acc[mt][0], al[mt], bh0);
                mma_bf16(acc[mt][1], ah[mt], bh1);
                mma_bf16(acc[mt][1], ah[mt], bl1);
                mma_bf16(acc[mt][1], al[mt], bh1);
            }
        }
    }

    #pragma unroll
    for (int mt = 0; mt < 4; mt++) {
        #pragma unroll
        for (int h = 0; h < 2; h++) {
            const int row = m0 + wm * 64 + mt * 16 + g + h * 8;
            const size_t base = (size_t)row * ldo;
            #pragma unroll
            for (int nt = 0; nt < 2; nt++) {
                const int col = n0 + wn * 16 + nt * 8 + tig * 2;
                const float d0 = acc[mt][nt][h * 2 + 0];
                const float d1 = acc[mt][nt][h * 2 + 1];
                if (STEP) {
                    float2 ib = *reinterpret_cast<const float2*>(aux0 + base + col);
                    float2 hf = *reinterpret_cast<const float2*>(aux1 + base + col);
                    const float dc0 = colv[col - n0];
                    const float dc1 = colv[col - n0 + 1];
                    const float hn0 = dc0 * hf.x + (1.0f - dc0) * tanh_acc(d0 + ib.x);
                    const float hn1 = dc1 * hf.y + (1.0f - dc1) * tanh_acc(d1 + ib.y);
                    *reinterpret_cast<float2*>(out_full + base + col) = make_float2(hn0, hn1);
                    __nv_bfloat162 hp, lp;
                    split1(hn0, hp.x, lp.x);
                    split1(hn1, hp.y, lp.y);
                    *reinterpret_cast<__nv_bfloat162*>(out_hi + base + col) = hp;
                    *reinterpret_cast<__nv_bfloat162*>(out_lo + base + col) = lp;
                } else {
                    float2 o = make_float2(d0 + colv[col - n0], d1 + colv[col - n0 + 1]);
                    *reinterpret_cast<float2*>(out_full + base + col) = o;
                }
            }
        }
    }
}

extern "C" void kernel_launch(void* const* d_in, const int* in_sizes, int n_in,
                              void* d_out, int out_size) {
    (void)in_sizes; (void)n_in; (void)out_size;
    const float* x   = (const float*)d_in[0];
    const float* h0  = (const float*)d_in[1];
    const float* Wih = (const float*)d_in[2];
    const float* bih = (const float*)d_in[3];
    const float* Whh = (const float*)d_in[4];
    const float* bhh = (const float*)d_in[5];
    const float* tau = (const float*)d_in[6];
    float* out = (float*)d_out;

    float *p_ihb, *p_hfull;
    __nv_bfloat16 *p_hhiA, *p_hloA, *p_hhiB, *p_hloB;
    __nv_bfloat16 *p_xhi, *p_xlo, *p_wihhi, *p_wihlo, *p_whhhi, *p_whhlo;
    cudaGetSymbolAddress((void**)&p_ihb, g_ihb);
    cudaGetSymbolAddress((void**)&p_hfull, g_hfull);
    cudaGetSymbolAddress((void**)&p_hhiA, g_hhiA);
    cudaGetSymbolAddress((void**)&p_hloA, g_hloA);
    cudaGetSymbolAddress((void**)&p_hhiB, g_hhiB);
    cudaGetSymbolAddress((void**)&p_hloB, g_hloB);
    cudaGetSymbolAddress((void**)&p_xhi, g_xhi);
    cudaGetSymbolAddress((void**)&p_xlo, g_xlo);
    cudaGetSymbolAddress((void**)&p_wihhi, g_wihhi);
    cudaGetSymbolAddress((void**)&p_wihlo, g_wihlo);
    cudaGetSymbolAddress((void**)&p_whhhi, g_whhhi);
    cudaGetSymbolAddress((void**)&p_whhlo, g_whhlo);

    cudaFuncSetAttribute(gemm_kernel<false>, cudaFuncAttributeMaxDynamicSharedMemorySize, SMEM_TOTAL);
    cudaFuncSetAttribute(gemm_kernel<true>,  cudaFuncAttributeMaxDynamicSharedMemorySize, SMEM_TOTAL);

    prep_all_kernel<<<512, 256>>>(x, Wih, Whh, h0,
                                  p_xhi, p_xlo, p_wihhi, p_wihlo, p_whhhi, p_whhlo,
                                  p_hfull, p_hhiA, p_hloA);

    dim3 grid(HDIM / BN, BDIM / BM);
    gemm_kernel<false><<<grid, NT, SMEM_TOTAL>>>(p_xhi, p_xlo, p_wihhi, p_wihlo, IDIM,
                                                 bih, bhh, nullptr,
                                                 p_ihb, nullptr, nullptr, HDIM);
    __nv_bfloat16 *hi_in = p_hhiA, *lo_in = p_hloA;
    __nv_bfloat16 *hi_out = p_hhiB, *lo_out = p_hloB;
    for (int s = 0; s < NSTEPS; s++) {
        float* full_dst = (s == NSTEPS - 1) ? out : p_hfull;
        gemm_kernel<true><<<grid, NT, SMEM_TOTAL>>>(hi_in, lo_in, p_whhhi, p_whhlo, HDIM,
                                                    p_ihb, p_hfull, tau,
                                                    full_dst, hi_out, lo_out, HDIM);
        __nv_bfloat16* t;
        t = hi_in; hi_in = hi_out; hi_out = t;
        t = lo_in; lo_in = lo_out; lo_out = t;
    }
}